// round 1
// baseline (speedup 1.0000x reference)
#include <cuda_runtime.h>
#include <math.h>

#define NTOK  4096
#define DIM   1024
#define HID   2732
#define HPAD  2752          // HID padded to multiple of 64
#define NEXP  8
#define NSLOT 8192          // NTOK * TOPK

// ---------------- scratch (static device globals; no allocs allowed) --------
__device__ float g_h[(size_t)NSLOT * HPAD];   // ~90 MB  SwiGLU activations
__device__ float g_y[(size_t)NSLOT * DIM];    // ~33 MB  per-slot expert output
__device__ int   g_expert[NSLOT];
__device__ float g_wslot[NSLOT];
__device__ int   g_counts[NEXP];
__device__ int   g_off[NEXP];
__device__ int   g_cursor[NEXP];
__device__ int   g_tok[NSLOT];     // sorted position -> token id
__device__ int   g_rowof[NSLOT];   // slot (tok*2+k) -> sorted position

// ---------------- tiny bookkeeping kernels ----------------------------------
__global__ void k_zero() {
    int t = threadIdx.x;
    if (t < NEXP) g_counts[t] = 0;
}

__global__ void k_scan() {
    if (threadIdx.x == 0) {
        int s = 0;
        for (int e = 0; e < NEXP; e++) { g_off[e] = s; g_cursor[e] = s; s += g_counts[e]; }
    }
}

__global__ void k_scatter() {
    int s = blockIdx.x * 256 + threadIdx.x;
    if (s < NSLOT) {
        int e = g_expert[s];
        int pos = atomicAdd(&g_cursor[e], 1);
        g_tok[pos]  = s >> 1;
        g_rowof[s]  = pos;
    }
}

// ---------------- routing: scores = x @ Wg^T, top-2 + softmax ---------------
__global__ void k_route(const float* __restrict__ x, const float* __restrict__ wg) {
    __shared__ float4 s_wg[NEXP * DIM / 4];           // 32 KB
    int tid = threadIdx.x;                            // 256
    const float4* wg4 = (const float4*)wg;
    for (int i = tid; i < NEXP * DIM / 4; i += 256) s_wg[i] = wg4[i];
    __syncthreads();

    int warp = tid >> 5, lane = tid & 31;
    int tok  = blockIdx.x * 8 + warp;
    if (tok >= NTOK) return;

    const float4* xr = (const float4*)(x + (size_t)tok * DIM);
    float acc[NEXP];
#pragma unroll
    for (int e = 0; e < NEXP; e++) acc[e] = 0.f;

    for (int j = lane; j < DIM / 4; j += 32) {
        float4 xv = xr[j];
#pragma unroll
        for (int e = 0; e < NEXP; e++) {
            float4 w = s_wg[e * (DIM / 4) + j];
            acc[e] += xv.x * w.x + xv.y * w.y + xv.z * w.z + xv.w * w.w;
        }
    }
#pragma unroll
    for (int e = 0; e < NEXP; e++)
        for (int o = 16; o; o >>= 1) acc[e] += __shfl_xor_sync(0xffffffffu, acc[e], o);

    if (lane == 0) {
        int e0 = 0;
#pragma unroll
        for (int e = 1; e < NEXP; e++) if (acc[e] > acc[e0]) e0 = e;
        int e1 = (e0 == 0) ? 1 : 0;
#pragma unroll
        for (int e = 0; e < NEXP; e++) if (e != e0 && acc[e] > acc[e1]) e1 = e;
        float p1  = expf(acc[e1] - acc[e0]);
        float inv = 1.f / (1.f + p1);
        g_expert[2 * tok]     = e0;  g_wslot[2 * tok]     = inv;
        g_expert[2 * tok + 1] = e1;  g_wslot[2 * tok + 1] = p1 * inv;
        atomicAdd(&g_counts[e0], 1);
        atomicAdd(&g_counts[e1], 1);
    }
}

// ---------------- GEMM1: h = silu(X@W1^T) * (X@W3^T)  [grouped, gathered A] -
// grid: (HPAD/64, 32, NEXP), block 256.  BM=128, BN=64, BK=16.
__global__ void __launch_bounds__(256, 2)
k_gemm1(const float* __restrict__ x, const float* __restrict__ W1,
        const float* __restrict__ W3) {
    int e    = blockIdx.z;
    int ne   = g_counts[e];
    int row0 = blockIdx.y * 128;
    if (row0 >= ne) return;
    int base = g_off[e];
    int col0 = blockIdx.x * 64;

    __shared__ float As [16][132];
    __shared__ float Bs1[16][68];
    __shared__ float Bs3[16][68];

    int tid = threadIdx.x;

    // A-tile loader assignments (2 float4 per thread, gathered rows)
    int ar[2], aq[2];
    const float* ap[2];
#pragma unroll
    for (int i = 0; i < 2; i++) {
        int idx = tid + 256 * i;
        ar[i] = idx >> 2;
        aq[i] = idx & 3;
        int r = row0 + ar[i];
        int t = g_tok[base + min(r, ne - 1)];
        ap[i] = x + (size_t)t * DIM + aq[i] * 4;
    }
    // B-tile loader: 1 float4 per thread per matrix
    int  br = tid >> 2, bq = tid & 3;
    int  n  = col0 + br;
    int  nc = min(n, HID - 1);
    bool nv = (n < HID);
    const float* p1 = W1 + ((size_t)e * HID + nc) * DIM + bq * 4;
    const float* p3 = W3 + ((size_t)e * HID + nc) * DIM + bq * 4;

    int ty = tid >> 4, tx = tid & 15;
    float acc1[8][4], acc3[8][4];
#pragma unroll
    for (int im = 0; im < 8; im++)
#pragma unroll
        for (int jn = 0; jn < 4; jn++) { acc1[im][jn] = 0.f; acc3[im][jn] = 0.f; }

    for (int k0 = 0; k0 < DIM; k0 += 16) {
#pragma unroll
        for (int i = 0; i < 2; i++) {
            float4 v = *(const float4*)(ap[i] + k0);
            int q = aq[i] * 4;
            As[q + 0][ar[i]] = v.x; As[q + 1][ar[i]] = v.y;
            As[q + 2][ar[i]] = v.z; As[q + 3][ar[i]] = v.w;
        }
        float4 v1 = nv ? *(const float4*)(p1 + k0) : make_float4(0, 0, 0, 0);
        float4 v3 = nv ? *(const float4*)(p3 + k0) : make_float4(0, 0, 0, 0);
        {
            int q = bq * 4;
            Bs1[q + 0][br] = v1.x; Bs1[q + 1][br] = v1.y;
            Bs1[q + 2][br] = v1.z; Bs1[q + 3][br] = v1.w;
            Bs3[q + 0][br] = v3.x; Bs3[q + 1][br] = v3.y;
            Bs3[q + 2][br] = v3.z; Bs3[q + 3][br] = v3.w;
        }
        __syncthreads();
#pragma unroll
        for (int k = 0; k < 16; k++) {
            float4 a0 = *(const float4*)&As [k][ty * 8];
            float4 a1 = *(const float4*)&As [k][ty * 8 + 4];
            float4 b1 = *(const float4*)&Bs1[k][tx * 4];
            float4 b3 = *(const float4*)&Bs3[k][tx * 4];
            float a[8]  = {a0.x, a0.y, a0.z, a0.w, a1.x, a1.y, a1.z, a1.w};
            float c1[4] = {b1.x, b1.y, b1.z, b1.w};
            float c3[4] = {b3.x, b3.y, b3.z, b3.w};
#pragma unroll
            for (int im = 0; im < 8; im++)
#pragma unroll
                for (int jn = 0; jn < 4; jn++) {
                    acc1[im][jn] += a[im] * c1[jn];
                    acc3[im][jn] += a[im] * c3[jn];
                }
        }
        __syncthreads();
    }

    // epilogue: SwiGLU, write padded h (pad cols naturally 0)
#pragma unroll
    for (int im = 0; im < 8; im++) {
        int r = row0 + ty * 8 + im;
        if (r < ne) {
            int pos = base + r;
            float v[4];
#pragma unroll
            for (int jn = 0; jn < 4; jn++) {
                float z = acc1[im][jn];
                float t = acc3[im][jn];
                v[jn] = (z / (1.f + expf(-z))) * t;
            }
            *(float4*)&g_h[(size_t)pos * HPAD + col0 + tx * 4] =
                make_float4(v[0], v[1], v[2], v[3]);
        }
    }
}

// ---------------- GEMM2: y = h @ W2^T  [grouped, contiguous A] --------------
// grid: (DIM/64, 32, NEXP), block 256.  BM=128, BN=64, BK=16, K=HPAD.
__global__ void __launch_bounds__(256, 2)
k_gemm2(const float* __restrict__ W2) {
    int e    = blockIdx.z;
    int ne   = g_counts[e];
    int row0 = blockIdx.y * 128;
    if (row0 >= ne) return;
    int base = g_off[e];
    int col0 = blockIdx.x * 64;

    __shared__ float As[16][132];
    __shared__ float Bs[16][68];

    int tid = threadIdx.x;
    int ar[2], aq[2];
    const float* ap[2];
#pragma unroll
    for (int i = 0; i < 2; i++) {
        int idx = tid + 256 * i;
        ar[i] = idx >> 2;
        aq[i] = idx & 3;
        int r = min(row0 + ar[i], ne - 1);
        ap[i] = g_h + (size_t)(base + r) * HPAD + aq[i] * 4;
    }
    int br = tid >> 2, bq = tid & 3;
    int d  = col0 + br;                                   // always < DIM
    const float* bp = W2 + ((size_t)e * DIM + d) * HID + bq * 4;

    int ty = tid >> 4, tx = tid & 15;
    float acc[8][4];
#pragma unroll
    for (int im = 0; im < 8; im++)
#pragma unroll
        for (int jn = 0; jn < 4; jn++) acc[im][jn] = 0.f;

    for (int k0 = 0; k0 < HPAD; k0 += 16) {
#pragma unroll
        for (int i = 0; i < 2; i++) {
            float4 v = *(const float4*)(ap[i] + k0);
            int q = aq[i] * 4;
            As[q + 0][ar[i]] = v.x; As[q + 1][ar[i]] = v.y;
            As[q + 2][ar[i]] = v.z; As[q + 3][ar[i]] = v.w;
        }
        {
            int kk = k0 + bq * 4;                         // HID % 4 == 0 -> quad granular
            float4 bv = (kk < HID) ? *(const float4*)(bp + k0)
                                   : make_float4(0, 0, 0, 0);
            int q = bq * 4;
            Bs[q + 0][br] = bv.x; Bs[q + 1][br] = bv.y;
            Bs[q + 2][br] = bv.z; Bs[q + 3][br] = bv.w;
        }
        __syncthreads();
#pragma unroll
        for (int k = 0; k < 16; k++) {
            float4 a0 = *(const float4*)&As[k][ty * 8];
            float4 a1 = *(const float4*)&As[k][ty * 8 + 4];
            float4 bv = *(const float4*)&Bs[k][tx * 4];
            float a[8] = {a0.x, a0.y, a0.z, a0.w, a1.x, a1.y, a1.z, a1.w};
            float b[4] = {bv.x, bv.y, bv.z, bv.w};
#pragma unroll
            for (int im = 0; im < 8; im++)
#pragma unroll
                for (int jn = 0; jn < 4; jn++)
                    acc[im][jn] += a[im] * b[jn];
        }
        __syncthreads();
    }

#pragma unroll
    for (int im = 0; im < 8; im++) {
        int r = row0 + ty * 8 + im;
        if (r < ne) {
            *(float4*)&g_y[(size_t)(base + r) * DIM + col0 + tx * 4] =
                make_float4(acc[im][0], acc[im][1], acc[im][2], acc[im][3]);
        }
    }
}

// ---------------- combine: out[tok] = w0*y[row0] + w1*y[row1] ---------------
__global__ void k_combine(float* __restrict__ out) {
    int tok = blockIdx.x;
    int tid = threadIdx.x;                    // 256 = DIM/4
    int r0 = g_rowof[2 * tok], r1 = g_rowof[2 * tok + 1];
    float w0 = g_wslot[2 * tok], w1 = g_wslot[2 * tok + 1];
    float4 y0 = ((const float4*)(g_y + (size_t)r0 * DIM))[tid];
    float4 y1 = ((const float4*)(g_y + (size_t)r1 * DIM))[tid];
    float4 o;
    o.x = w0 * y0.x + w1 * y1.x;
    o.y = w0 * y0.y + w1 * y1.y;
    o.z = w0 * y0.z + w1 * y1.z;
    o.w = w0 * y0.w + w1 * y1.w;
    ((float4*)(out + (size_t)tok * DIM))[tid] = o;
}

// ---------------- launch -----------------------------------------------------
extern "C" void kernel_launch(void* const* d_in, const int* in_sizes, int n_in,
                              void* d_out, int out_size) {
    const float* x  = (const float*)d_in[0];
    const float* Wg = (const float*)d_in[1];
    const float* W1 = (const float*)d_in[2];
    const float* W2 = (const float*)d_in[3];
    const float* W3 = (const float*)d_in[4];
    float* out = (float*)d_out;
    (void)in_sizes; (void)n_in; (void)out_size;

    k_zero   <<<1, 32>>>();
    k_route  <<<NTOK / 8, 256>>>(x, Wg);
    k_scan   <<<1, 32>>>();
    k_scatter<<<NSLOT / 256, 256>>>();
    k_gemm1  <<<dim3(HPAD / 64, NTOK / 128, NEXP), 256>>>(x, W1, W3);
    k_gemm2  <<<dim3(DIM / 64, NTOK / 128, NEXP), 256>>>(W2);
    k_combine<<<NTOK, 256>>>(out);
}

// round 2
// speedup vs baseline: 2.7553x; 2.7553x over previous
#include <cuda_runtime.h>
#include <math.h>

#define NTOK  4096
#define DIM   1024
#define HID   2732
#define HPAD  2752          // HID padded to multiple of 64
#define NEXP  8
#define NSLOT 8192          // NTOK * TOPK
#define BK    16
#define LDSB  20            // smem row stride (floats): 16 data + 4 pad -> conflict-free LDSM

// ---------------- scratch (static device globals; no allocs allowed) --------
__device__ float g_h[(size_t)NSLOT * HPAD];   // ~90 MB  SwiGLU activations (tf32-rounded)
__device__ float g_y[(size_t)NSLOT * DIM];    // ~33 MB  per-slot expert output
__device__ int   g_expert[NSLOT];
__device__ float g_wslot[NSLOT];
__device__ int   g_counts[NEXP];
__device__ int   g_off[NEXP];
__device__ int   g_cursor[NEXP];
__device__ int   g_tok[NSLOT];     // sorted position -> token id
__device__ int   g_rowof[NSLOT];   // slot (tok*2+k) -> sorted position

// ---------------- PTX helpers ------------------------------------------------
__device__ __forceinline__ unsigned smem_u32(const void* p) {
    return (unsigned)__cvta_generic_to_shared(p);
}
__device__ __forceinline__ void cp16(unsigned dst, const void* src) {
    asm volatile("cp.async.cg.shared.global [%0], [%1], 16;" :: "r"(dst), "l"(src));
}
__device__ __forceinline__ void cp16z(unsigned dst, const void* src, int src_sz) {
    asm volatile("cp.async.cg.shared.global [%0], [%1], 16, %2;"
                 :: "r"(dst), "l"(src), "r"(src_sz));
}
__device__ __forceinline__ void cp_commit() { asm volatile("cp.async.commit_group;"); }
__device__ __forceinline__ void cp_wait1()  { asm volatile("cp.async.wait_group 1;"); }
__device__ __forceinline__ void cp_wait0()  { asm volatile("cp.async.wait_group 0;"); }

__device__ __forceinline__ void ldsm_x4(unsigned addr, unsigned& r0, unsigned& r1,
                                        unsigned& r2, unsigned& r3) {
    asm volatile("ldmatrix.sync.aligned.m8n8.x4.shared.b16 {%0,%1,%2,%3}, [%4];"
                 : "=r"(r0), "=r"(r1), "=r"(r2), "=r"(r3) : "r"(addr));
}
// round f32 -> tf32 bit pattern (round-to-nearest: keeps errors zero-mean)
__device__ __forceinline__ unsigned f2tf_f(float f) {
    unsigned r; asm("cvt.rna.tf32.f32 %0, %1;" : "=r"(r) : "f"(f)); return r;
}
__device__ __forceinline__ unsigned f2tf_u(unsigned u) {
    return f2tf_f(__uint_as_float(u));
}
__device__ __forceinline__ void mma_tf32(float* c, const unsigned* a, unsigned b0, unsigned b1) {
    asm volatile(
        "mma.sync.aligned.m16n8k8.row.col.f32.tf32.tf32.f32 "
        "{%0,%1,%2,%3}, {%4,%5,%6,%7}, {%8,%9}, {%0,%1,%2,%3};"
        : "+f"(c[0]), "+f"(c[1]), "+f"(c[2]), "+f"(c[3])
        : "r"(a[0]), "r"(a[1]), "r"(a[2]), "r"(a[3]), "r"(b0), "r"(b1));
}

// ---------------- tiny bookkeeping kernels ----------------------------------
__global__ void k_zero() {
    int t = threadIdx.x;
    if (t < NEXP) g_counts[t] = 0;
}
__global__ void k_scan() {
    if (threadIdx.x == 0) {
        int s = 0;
        for (int e = 0; e < NEXP; e++) { g_off[e] = s; g_cursor[e] = s; s += g_counts[e]; }
    }
}
__global__ void k_scatter() {
    int s = blockIdx.x * 256 + threadIdx.x;
    if (s < NSLOT) {
        int e = g_expert[s];
        int pos = atomicAdd(&g_cursor[e], 1);
        g_tok[pos] = s >> 1;
        g_rowof[s] = pos;
    }
}

// ---------------- routing: scores = x @ Wg^T, top-2 + softmax ---------------
__global__ void k_route(const float* __restrict__ x, const float* __restrict__ wg) {
    __shared__ float4 s_wg[NEXP * DIM / 4];
    int tid = threadIdx.x;
    const float4* wg4 = (const float4*)wg;
    for (int i = tid; i < NEXP * DIM / 4; i += 256) s_wg[i] = wg4[i];
    __syncthreads();

    int warp = tid >> 5, lane = tid & 31;
    int tok = blockIdx.x * 8 + warp;
    if (tok >= NTOK) return;

    const float4* xr = (const float4*)(x + (size_t)tok * DIM);
    float acc[NEXP];
#pragma unroll
    for (int e = 0; e < NEXP; e++) acc[e] = 0.f;

    for (int j = lane; j < DIM / 4; j += 32) {
        float4 xv = xr[j];
#pragma unroll
        for (int e = 0; e < NEXP; e++) {
            float4 w = s_wg[e * (DIM / 4) + j];
            acc[e] += xv.x * w.x + xv.y * w.y + xv.z * w.z + xv.w * w.w;
        }
    }
#pragma unroll
    for (int e = 0; e < NEXP; e++)
        for (int o = 16; o; o >>= 1) acc[e] += __shfl_xor_sync(0xffffffffu, acc[e], o);

    if (lane == 0) {
        int e0 = 0;
#pragma unroll
        for (int e = 1; e < NEXP; e++) if (acc[e] > acc[e0]) e0 = e;
        int e1 = (e0 == 0) ? 1 : 0;
#pragma unroll
        for (int e = 0; e < NEXP; e++) if (e != e0 && acc[e] > acc[e1]) e1 = e;
        float p1  = expf(acc[e1] - acc[e0]);
        float inv = 1.f / (1.f + p1);
        g_expert[2 * tok]     = e0;  g_wslot[2 * tok]     = inv;
        g_expert[2 * tok + 1] = e1;  g_wslot[2 * tok + 1] = p1 * inv;
        atomicAdd(&g_counts[e0], 1);
        atomicAdd(&g_counts[e1], 1);
    }
}

// ---------------- GEMM1: h = silu(X@W1^T) * (X@W3^T)  tf32 tensor cores -----
// grid (HPAD/64, 64, NEXP), block 256. BM=128, BN=64 per matrix, BK=16.
__global__ void __launch_bounds__(256, 2)
k_gemm1(const float* __restrict__ x, const float* __restrict__ W1,
        const float* __restrict__ W3) {
    int e    = blockIdx.z;
    int ne   = g_counts[e];
    int row0 = blockIdx.y * 128;
    if (row0 >= ne) return;
    int base = g_off[e];
    int col0 = blockIdx.x * 64;

    __shared__ float sA [2][128][LDSB];
    __shared__ float sB1[2][64][LDSB];
    __shared__ float sB3[2][64][LDSB];

    int tid = threadIdx.x;

    // A loaders: 2 x 16B chunks per thread (gathered token rows)
    const float* aptr[2];
    int arow[2], aseg[2];
#pragma unroll
    for (int i = 0; i < 2; i++) {
        int c = tid + 256 * i;
        arow[i] = c >> 2; aseg[i] = c & 3;
        int r = min(row0 + arow[i], ne - 1);
        int t = g_tok[base + r];
        aptr[i] = x + (size_t)t * DIM + aseg[i] * 4;
    }
    // B loaders: 1 chunk per thread per matrix
    int brow = tid >> 2, bseg = tid & 3;
    int n  = col0 + brow;
    int nvalid = (n < HID) ? 16 : 0;
    int nc = min(n, HID - 1);
    const float* b1p = W1 + ((size_t)e * HID + nc) * DIM + bseg * 4;
    const float* b3p = W3 + ((size_t)e * HID + nc) * DIM + bseg * 4;

    int w = tid >> 5, lane = tid & 31;
    int wm = w >> 1, wn = w & 1;                 // 4 x 2 warp grid
    int a_r = lane & 15, a_k = (lane >> 4) << 2;
    int b_r = ((lane >> 4) << 3) + (lane & 7);
    int b_k = ((lane >> 3) & 1) << 2;

    float acc1[2][4][4], acc3[2][4][4];
#pragma unroll
    for (int ms = 0; ms < 2; ms++)
#pragma unroll
        for (int ns = 0; ns < 4; ns++)
#pragma unroll
            for (int i = 0; i < 4; i++) { acc1[ms][ns][i] = 0.f; acc3[ms][ns][i] = 0.f; }

    // prologue: stage 0
#pragma unroll
    for (int i = 0; i < 2; i++)
        cp16(smem_u32(&sA[0][arow[i]][aseg[i] * 4]), aptr[i]);
    cp16z(smem_u32(&sB1[0][brow][bseg * 4]), b1p, nvalid);
    cp16z(smem_u32(&sB3[0][brow][bseg * 4]), b3p, nvalid);
    cp_commit();

    const int NIT = DIM / BK;   // 64
    int cur = 0;
    for (int it = 0; it < NIT; it++) {
        if (it + 1 < NIT) {
            int k0 = (it + 1) * BK;
            int nst = cur ^ 1;
#pragma unroll
            for (int i = 0; i < 2; i++)
                cp16(smem_u32(&sA[nst][arow[i]][aseg[i] * 4]), aptr[i] + k0);
            cp16z(smem_u32(&sB1[nst][brow][bseg * 4]), b1p + k0, nvalid);
            cp16z(smem_u32(&sB3[nst][brow][bseg * 4]), b3p + k0, nvalid);
            cp_commit();
            cp_wait1();
        } else {
            cp_wait0();
        }
        __syncthreads();

#pragma unroll
        for (int ks = 0; ks < 2; ks++) {
            unsigned a[2][4];
#pragma unroll
            for (int ms = 0; ms < 2; ms++) {
                int m = wm * 32 + ms * 16;
                ldsm_x4(smem_u32(&sA[cur][m + a_r][ks * 8 + a_k]),
                        a[ms][0], a[ms][1], a[ms][2], a[ms][3]);
#pragma unroll
                for (int i = 0; i < 4; i++) a[ms][i] = f2tf_u(a[ms][i]);
            }
            unsigned b1r[4][2], b3r[4][2];
#pragma unroll
            for (int ns2 = 0; ns2 < 2; ns2++) {
                int nn = wn * 32 + ns2 * 16;
                unsigned r0, r1, r2, r3;
                ldsm_x4(smem_u32(&sB1[cur][nn + b_r][ks * 8 + b_k]), r0, r1, r2, r3);
                b1r[ns2*2][0] = f2tf_u(r0); b1r[ns2*2][1] = f2tf_u(r1);
                b1r[ns2*2+1][0] = f2tf_u(r2); b1r[ns2*2+1][1] = f2tf_u(r3);
                ldsm_x4(smem_u32(&sB3[cur][nn + b_r][ks * 8 + b_k]), r0, r1, r2, r3);
                b3r[ns2*2][0] = f2tf_u(r0); b3r[ns2*2][1] = f2tf_u(r1);
                b3r[ns2*2+1][0] = f2tf_u(r2); b3r[ns2*2+1][1] = f2tf_u(r3);
            }
#pragma unroll
            for (int ms = 0; ms < 2; ms++)
#pragma unroll
                for (int ns = 0; ns < 4; ns++) {
                    mma_tf32(acc1[ms][ns], a[ms], b1r[ns][0], b1r[ns][1]);
                    mma_tf32(acc3[ms][ns], a[ms], b3r[ns][0], b3r[ns][1]);
                }
        }
        __syncthreads();
        cur ^= 1;
    }

    // epilogue: SwiGLU, tf32-round, write padded h
    int crow = lane >> 2, ccol = (lane & 3) * 2;
#pragma unroll
    for (int ms = 0; ms < 2; ms++) {
#pragma unroll
        for (int half = 0; half < 2; half++) {
            int r = row0 + wm * 32 + ms * 16 + crow + half * 8;
            if (r < ne) {
                size_t rowbase = (size_t)(base + r) * HPAD;
#pragma unroll
                for (int ns = 0; ns < 4; ns++) {
                    int cc = col0 + wn * 32 + ns * 8 + ccol;
                    float z0 = acc1[ms][ns][half * 2 + 0];
                    float z1 = acc1[ms][ns][half * 2 + 1];
                    float t0 = acc3[ms][ns][half * 2 + 0];
                    float t1 = acc3[ms][ns][half * 2 + 1];
                    float v0 = (z0 / (1.f + __expf(-z0))) * t0;
                    float v1 = (z1 / (1.f + __expf(-z1))) * t1;
                    float2 o = make_float2(__uint_as_float(f2tf_f(v0)),
                                           __uint_as_float(f2tf_f(v1)));
                    *(float2*)&g_h[rowbase + cc] = o;
                }
            }
        }
    }
}

// ---------------- GEMM2: y = h @ W2^T  tf32 tensor cores --------------------
// grid (DIM/64, 64, NEXP), block 256. BM=128, BN=64, BK=16, K=HPAD.
__global__ void __launch_bounds__(256, 2)
k_gemm2(const float* __restrict__ W2) {
    int e    = blockIdx.z;
    int ne   = g_counts[e];
    int row0 = blockIdx.y * 128;
    if (row0 >= ne) return;
    int base = g_off[e];
    int col0 = blockIdx.x * 64;

    __shared__ float sA[2][128][LDSB];
    __shared__ float sB[2][64][LDSB];

    int tid = threadIdx.x;
    const float* aptr[2];
    int arow[2], aseg[2];
#pragma unroll
    for (int i = 0; i < 2; i++) {
        int c = tid + 256 * i;
        arow[i] = c >> 2; aseg[i] = c & 3;
        int r = min(row0 + arow[i], ne - 1);
        aptr[i] = g_h + (size_t)(base + r) * HPAD + aseg[i] * 4;
    }
    int brow = tid >> 2, bseg = tid & 3;
    int d = col0 + brow;                                   // < DIM always
    const float* bp = W2 + ((size_t)e * DIM + d) * HID + bseg * 4;

    int w = tid >> 5, lane = tid & 31;
    int wm = w >> 1, wn = w & 1;
    int a_r = lane & 15, a_k = (lane >> 4) << 2;
    int b_r = ((lane >> 4) << 3) + (lane & 7);
    int b_k = ((lane >> 3) & 1) << 2;

    float acc[2][4][4];
#pragma unroll
    for (int ms = 0; ms < 2; ms++)
#pragma unroll
        for (int ns = 0; ns < 4; ns++)
#pragma unroll
            for (int i = 0; i < 4; i++) acc[ms][ns][i] = 0.f;

    // prologue
#pragma unroll
    for (int i = 0; i < 2; i++)
        cp16(smem_u32(&sA[0][arow[i]][aseg[i] * 4]), aptr[i]);
    cp16z(smem_u32(&sB[0][brow][bseg * 4]), bp, ((0 + bseg * 4) < HID) ? 16 : 0);
    cp_commit();

    const int NIT = HPAD / BK;   // 172
    int cur = 0;
    for (int it = 0; it < NIT; it++) {
        if (it + 1 < NIT) {
            int k0 = (it + 1) * BK;
            int nst = cur ^ 1;
#pragma unroll
            for (int i = 0; i < 2; i++)
                cp16(smem_u32(&sA[nst][arow[i]][aseg[i] * 4]), aptr[i] + k0);
            cp16z(smem_u32(&sB[nst][brow][bseg * 4]), bp + k0,
                  ((k0 + bseg * 4) < HID) ? 16 : 0);
            cp_commit();
            cp_wait1();
        } else {
            cp_wait0();
        }
        __syncthreads();

#pragma unroll
        for (int ks = 0; ks < 2; ks++) {
            unsigned a[2][4];
#pragma unroll
            for (int ms = 0; ms < 2; ms++) {
                int m = wm * 32 + ms * 16;
                ldsm_x4(smem_u32(&sA[cur][m + a_r][ks * 8 + a_k]),
                        a[ms][0], a[ms][1], a[ms][2], a[ms][3]);
                // g_h already tf32-rounded: no cvt needed
            }
            unsigned br[4][2];
#pragma unroll
            for (int ns2 = 0; ns2 < 2; ns2++) {
                int nn = wn * 32 + ns2 * 16;
                unsigned r0, r1, r2, r3;
                ldsm_x4(smem_u32(&sB[cur][nn + b_r][ks * 8 + b_k]), r0, r1, r2, r3);
                br[ns2*2][0] = f2tf_u(r0); br[ns2*2][1] = f2tf_u(r1);
                br[ns2*2+1][0] = f2tf_u(r2); br[ns2*2+1][1] = f2tf_u(r3);
            }
#pragma unroll
            for (int ms = 0; ms < 2; ms++)
#pragma unroll
                for (int ns = 0; ns < 4; ns++)
                    mma_tf32(acc[ms][ns], a[ms], br[ns][0], br[ns][1]);
        }
        __syncthreads();
        cur ^= 1;
    }

    int crow = lane >> 2, ccol = (lane & 3) * 2;
#pragma unroll
    for (int ms = 0; ms < 2; ms++) {
#pragma unroll
        for (int half = 0; half < 2; half++) {
            int r = row0 + wm * 32 + ms * 16 + crow + half * 8;
            if (r < ne) {
                size_t rowbase = (size_t)(base + r) * DIM;
#pragma unroll
                for (int ns = 0; ns < 4; ns++) {
                    int cc = col0 + wn * 32 + ns * 8 + ccol;
                    float2 o = make_float2(acc[ms][ns][half * 2 + 0],
                                           acc[ms][ns][half * 2 + 1]);
                    *(float2*)&g_y[rowbase + cc] = o;
                }
            }
        }
    }
}

// ---------------- combine: out[tok] = w0*y[row0] + w1*y[row1] ---------------
__global__ void k_combine(float* __restrict__ out) {
    int tok = blockIdx.x;
    int tid = threadIdx.x;                    // 256 = DIM/4
    int r0 = g_rowof[2 * tok], r1 = g_rowof[2 * tok + 1];
    float w0 = g_wslot[2 * tok], w1 = g_wslot[2 * tok + 1];
    float4 y0 = ((const float4*)(g_y + (size_t)r0 * DIM))[tid];
    float4 y1 = ((const float4*)(g_y + (size_t)r1 * DIM))[tid];
    float4 o;
    o.x = w0 * y0.x + w1 * y1.x;
    o.y = w0 * y0.y + w1 * y1.y;
    o.z = w0 * y0.z + w1 * y1.z;
    o.w = w0 * y0.w + w1 * y1.w;
    ((float4*)(out + (size_t)tok * DIM))[tid] = o;
}

// ---------------- launch -----------------------------------------------------
extern "C" void kernel_launch(void* const* d_in, const int* in_sizes, int n_in,
                              void* d_out, int out_size) {
    const float* x  = (const float*)d_in[0];
    const float* Wg = (const float*)d_in[1];
    const float* W1 = (const float*)d_in[2];
    const float* W2 = (const float*)d_in[3];
    const float* W3 = (const float*)d_in[4];
    float* out = (float*)d_out;
    (void)in_sizes; (void)n_in; (void)out_size;

    k_zero   <<<1, 32>>>();
    k_route  <<<NTOK / 8, 256>>>(x, Wg);
    k_scan   <<<1, 32>>>();
    k_scatter<<<NSLOT / 256, 256>>>();
    k_gemm1  <<<dim3(HPAD / 64, NSLOT / 128, NEXP), 256>>>(x, W1, W3);
    k_gemm2  <<<dim3(DIM / 64, NSLOT / 128, NEXP), 256>>>(W2);
    k_combine<<<NTOK, 256>>>(out);
}

// round 4
// speedup vs baseline: 4.4316x; 1.6084x over previous
#include <cuda_runtime.h>
#include <cuda_fp16.h>
#include <math.h>
#include <stdint.h>

#define NTOK  4096
#define DIM   1024
#define HID   2732
#define HPAD  2752          // 43 * 64
#define NEXP  8
#define NSLOT 8192
#define BK    32            // K halves per stage
#define LDSH  40            // smem row stride in halves (80B): conflict-free ldsm

// ---------------- scratch (static device globals; no allocs allowed) --------
__device__ __half g_h  [(size_t)NSLOT * HPAD];          // 45 MB
__device__ float  g_y  [(size_t)NSLOT * DIM];           // 33 MB
__device__ __half g_xh [(size_t)NTOK * DIM];
__device__ __half g_w1h[(size_t)NEXP * HID * DIM];      // 44.8 MB
__device__ __half g_w3h[(size_t)NEXP * HID * DIM];
__device__ __half g_w2h[(size_t)NEXP * DIM * HPAD];     // padded rows
__device__ int    g_expert[NSLOT];
__device__ float  g_wslot[NSLOT];
__device__ int    g_counts[NEXP];
__device__ int    g_off[NEXP];
__device__ int    g_cursor[NEXP];
__device__ int    g_tok[NSLOT];
__device__ int    g_rowof[NSLOT];

// ---------------- PTX helpers ------------------------------------------------
__device__ __forceinline__ unsigned smem_u32(const void* p) {
    return (unsigned)__cvta_generic_to_shared(p);
}
__device__ __forceinline__ void cp16(unsigned dst, const void* src) {
    asm volatile("cp.async.cg.shared.global [%0], [%1], 16;" :: "r"(dst), "l"(src));
}
__device__ __forceinline__ void cp16z(unsigned dst, const void* src, int sz) {
    asm volatile("cp.async.cg.shared.global [%0], [%1], 16, %2;"
                 :: "r"(dst), "l"(src), "r"(sz));
}
__device__ __forceinline__ void cp_commit() { asm volatile("cp.async.commit_group;"); }
__device__ __forceinline__ void cp_wait1()  { asm volatile("cp.async.wait_group 1;"); }
__device__ __forceinline__ void cp_wait0()  { asm volatile("cp.async.wait_group 0;"); }

__device__ __forceinline__ void ldsm_x4(unsigned addr, unsigned& r0, unsigned& r1,
                                        unsigned& r2, unsigned& r3) {
    asm volatile("ldmatrix.sync.aligned.m8n8.x4.shared.b16 {%0,%1,%2,%3}, [%4];"
                 : "=r"(r0), "=r"(r1), "=r"(r2), "=r"(r3) : "r"(addr));
}
__device__ __forceinline__ void mma_f16(float* c, const unsigned* a, unsigned b0, unsigned b1) {
    asm volatile(
        "mma.sync.aligned.m16n8k16.row.col.f32.f16.f16.f32 "
        "{%0,%1,%2,%3}, {%4,%5,%6,%7}, {%8,%9}, {%0,%1,%2,%3};"
        : "+f"(c[0]), "+f"(c[1]), "+f"(c[2]), "+f"(c[3])
        : "r"(a[0]), "r"(a[1]), "r"(a[2]), "r"(a[3]), "r"(b0), "r"(b1));
}

// ---------------- bookkeeping ------------------------------------------------
__global__ void k_zero() { if (threadIdx.x < NEXP) g_counts[threadIdx.x] = 0; }
__global__ void k_scan() {
    if (threadIdx.x == 0) {
        int s = 0;
        for (int e = 0; e < NEXP; e++) { g_off[e] = s; g_cursor[e] = s; s += g_counts[e]; }
    }
}
__global__ void k_scatter() {
    int s = blockIdx.x * 256 + threadIdx.x;
    if (s < NSLOT) {
        int pos = atomicAdd(&g_cursor[g_expert[s]], 1);
        g_tok[pos] = s >> 1;
        g_rowof[s] = pos;
    }
}
// f32 -> fp16 (rne) bulk convert
__global__ void k_half(const float2* __restrict__ src, __half2* __restrict__ dst, int n2) {
    int i = blockIdx.x * 256 + threadIdx.x;
    int stride = gridDim.x * 256;
    for (; i < n2; i += stride) dst[i] = __float22half2_rn(src[i]);
}
// W2 [E*DIM][HID] f32 -> [E*DIM][HPAD] fp16 (zero-padded rows)
__global__ void k_half_w2(const float* __restrict__ W2) {
    int i = blockIdx.x * 256 + threadIdx.x;
    int stride = gridDim.x * 256;
    const int n2 = NEXP * DIM * (HPAD / 2);
    for (; i < n2; i += stride) {
        int row = i / (HPAD / 2);
        int c2  = (i % (HPAD / 2)) * 2;
        __half2 v = __float2half2_rn(0.f);
        if (c2 < HID) v = __float22half2_rn(*(const float2*)(W2 + (size_t)row * HID + c2));
        ((__half2*)(g_w2h + (size_t)row * HPAD))[c2 / 2] = v;
    }
}

// ---------------- routing (f32) ---------------------------------------------
__global__ void k_route(const float* __restrict__ x, const float* __restrict__ wg) {
    __shared__ float4 s_wg[NEXP * DIM / 4];
    int tid = threadIdx.x;
    const float4* wg4 = (const float4*)wg;
    for (int i = tid; i < NEXP * DIM / 4; i += 256) s_wg[i] = wg4[i];
    __syncthreads();

    int warp = tid >> 5, lane = tid & 31;
    int tok = blockIdx.x * 8 + warp;
    if (tok >= NTOK) return;

    const float4* xr = (const float4*)(x + (size_t)tok * DIM);
    float acc[NEXP];
#pragma unroll
    for (int e = 0; e < NEXP; e++) acc[e] = 0.f;
    for (int j = lane; j < DIM / 4; j += 32) {
        float4 xv = xr[j];
#pragma unroll
        for (int e = 0; e < NEXP; e++) {
            float4 w = s_wg[e * (DIM / 4) + j];
            acc[e] += xv.x * w.x + xv.y * w.y + xv.z * w.z + xv.w * w.w;
        }
    }
#pragma unroll
    for (int e = 0; e < NEXP; e++)
        for (int o = 16; o; o >>= 1) acc[e] += __shfl_xor_sync(0xffffffffu, acc[e], o);

    if (lane == 0) {
        int e0 = 0;
#pragma unroll
        for (int e = 1; e < NEXP; e++) if (acc[e] > acc[e0]) e0 = e;
        int e1 = (e0 == 0) ? 1 : 0;
#pragma unroll
        for (int e = 0; e < NEXP; e++) if (e != e0 && acc[e] > acc[e1]) e1 = e;
        float p1  = expf(acc[e1] - acc[e0]);
        float inv = 1.f / (1.f + p1);
        g_expert[2 * tok]     = e0;  g_wslot[2 * tok]     = inv;
        g_expert[2 * tok + 1] = e1;  g_wslot[2 * tok + 1] = p1 * inv;
        atomicAdd(&g_counts[e0], 1);
        atomicAdd(&g_counts[e1], 1);
    }
}

// ---------------- GEMM1: h = silu(X@W1^T) * (X@W3^T)  fp16 m16n8k16 ---------
// grid (HPAD/64, NSLOT/128, NEXP), block 256. BM=128, BN=64/matrix, BK=32.
__global__ void __launch_bounds__(256, 2)
k_gemm1(const __half* __restrict__ xh, const __half* __restrict__ w1h,
        const __half* __restrict__ w3h) {
    int e    = blockIdx.z;
    int ne   = g_counts[e];
    int row0 = blockIdx.y * 128;
    if (row0 >= ne) return;
    int base = g_off[e];
    int col0 = blockIdx.x * 64;

    __shared__ __half sA [2][128][LDSH];
    __shared__ __half sB1[2][64][LDSH];
    __shared__ __half sB3[2][64][LDSH];

    int tid = threadIdx.x;

    // A loaders: 2 x 16B chunks / thread / stage (gathered token rows)
    const __half* aptr[2];
    int arow[2], aseg[2];
#pragma unroll
    for (int i = 0; i < 2; i++) {
        int c = tid + 256 * i;
        arow[i] = c >> 2; aseg[i] = c & 3;
        int r = min(row0 + arow[i], ne - 1);
        aptr[i] = xh + (size_t)g_tok[base + r] * DIM + aseg[i] * 8;
    }
    // B loaders: 1 chunk per thread per matrix
    int brow = tid >> 2, bseg = tid & 3;
    int n  = col0 + brow;
    int nv = (n < HID) ? 16 : 0;
    int nc = min(n, HID - 1);
    const __half* b1p = w1h + ((size_t)e * HID + nc) * DIM + bseg * 8;
    const __half* b3p = w3h + ((size_t)e * HID + nc) * DIM + bseg * 8;

    int w = tid >> 5, lane = tid & 31;
    int wm = w >> 1, wn = w & 1;                  // 4 x 2 warps
    int a_r = lane & 15, a_c = (lane >> 4) * 8;   // halves
    int b_r = ((lane >> 4) << 3) + (lane & 7);
    int b_c = ((lane >> 3) & 1) * 8;

    float acc1[2][4][4], acc3[2][4][4];
#pragma unroll
    for (int ms = 0; ms < 2; ms++)
#pragma unroll
        for (int ns = 0; ns < 4; ns++)
#pragma unroll
            for (int i = 0; i < 4; i++) { acc1[ms][ns][i] = 0.f; acc3[ms][ns][i] = 0.f; }

    // prologue
#pragma unroll
    for (int i = 0; i < 2; i++)
        cp16(smem_u32(&sA[0][arow[i]][aseg[i] * 8]), aptr[i]);
    cp16z(smem_u32(&sB1[0][brow][bseg * 8]), b1p, nv);
    cp16z(smem_u32(&sB3[0][brow][bseg * 8]), b3p, nv);
    cp_commit();

    const int NIT = DIM / BK;   // 32
    int cur = 0;
    for (int it = 0; it < NIT; it++) {
        if (it + 1 < NIT) {
            int k0 = (it + 1) * BK;
            int nst = cur ^ 1;
#pragma unroll
            for (int i = 0; i < 2; i++)
                cp16(smem_u32(&sA[nst][arow[i]][aseg[i] * 8]), aptr[i] + k0);
            cp16z(smem_u32(&sB1[nst][brow][bseg * 8]), b1p + k0, nv);
            cp16z(smem_u32(&sB3[nst][brow][bseg * 8]), b3p + k0, nv);
            cp_commit();
            cp_wait1();
        } else {
            cp_wait0();
        }
        __syncthreads();

#pragma unroll
        for (int ks = 0; ks < 2; ks++) {          // two k16 per BK=32
            unsigned a[2][4];
#pragma unroll
            for (int ms = 0; ms < 2; ms++) {
                int m = wm * 32 + ms * 16;
                ldsm_x4(smem_u32(&sA[cur][m + a_r][ks * 16 + a_c]),
                        a[ms][0], a[ms][1], a[ms][2], a[ms][3]);
            }
            unsigned b1r[4][2], b3r[4][2];
#pragma unroll
            for (int ns2 = 0; ns2 < 2; ns2++) {
                int nn = wn * 32 + ns2 * 16;
                unsigned r0, r1, r2, r3;
                ldsm_x4(smem_u32(&sB1[cur][nn + b_r][ks * 16 + b_c]), r0, r1, r2, r3);
                b1r[ns2*2][0] = r0; b1r[ns2*2][1] = r1;
                b1r[ns2*2+1][0] = r2; b1r[ns2*2+1][1] = r3;
                ldsm_x4(smem_u32(&sB3[cur][nn + b_r][ks * 16 + b_c]), r0, r1, r2, r3);
                b3r[ns2*2][0] = r0; b3r[ns2*2][1] = r1;
                b3r[ns2*2+1][0] = r2; b3r[ns2*2+1][1] = r3;
            }
#pragma unroll
            for (int ms = 0; ms < 2; ms++)
#pragma unroll
                for (int ns = 0; ns < 4; ns++) {
                    mma_f16(acc1[ms][ns], a[ms], b1r[ns][0], b1r[ns][1]);
                    mma_f16(acc3[ms][ns], a[ms], b3r[ns][0], b3r[ns][1]);
                }
        }
        __syncthreads();
        cur ^= 1;
    }

    // epilogue: SwiGLU -> fp16 h
    int crow = lane >> 2, ccol = (lane & 3) * 2;
#pragma unroll
    for (int ms = 0; ms < 2; ms++) {
#pragma unroll
        for (int half_ = 0; half_ < 2; half_++) {
            int r = row0 + wm * 32 + ms * 16 + crow + half_ * 8;
            if (r < ne) {
                __half* dst = g_h + (size_t)(base + r) * HPAD;
#pragma unroll
                for (int ns = 0; ns < 4; ns++) {
                    int cc = col0 + wn * 32 + ns * 8 + ccol;
                    float z0 = acc1[ms][ns][half_ * 2 + 0];
                    float z1 = acc1[ms][ns][half_ * 2 + 1];
                    float t0 = acc3[ms][ns][half_ * 2 + 0];
                    float t1 = acc3[ms][ns][half_ * 2 + 1];
                    float v0 = z0 / (1.f + __expf(-z0)) * t0;
                    float v1 = z1 / (1.f + __expf(-z1)) * t1;
                    *(__half2*)(dst + cc) = __float22half2_rn(make_float2(v0, v1));
                }
            }
        }
    }
}

// ---------------- GEMM2: y = h @ W2^T  fp16 m16n8k16 ------------------------
// grid (DIM/64, NSLOT/128, NEXP), block 256. BM=128, BN=64, BK=32, K=HPAD.
__global__ void __launch_bounds__(256, 2)
k_gemm2(const __half* __restrict__ w2h) {
    int e    = blockIdx.z;
    int ne   = g_counts[e];
    int row0 = blockIdx.y * 128;
    if (row0 >= ne) return;
    int base = g_off[e];
    int col0 = blockIdx.x * 64;

    __shared__ __half sA[2][128][LDSH];
    __shared__ __half sB[2][64][LDSH];

    int tid = threadIdx.x;
    const __half* aptr[2];
    int arow[2], aseg[2];
#pragma unroll
    for (int i = 0; i < 2; i++) {
        int c = tid + 256 * i;
        arow[i] = c >> 2; aseg[i] = c & 3;
        int r = min(row0 + arow[i], ne - 1);
        aptr[i] = g_h + (size_t)(base + r) * HPAD + aseg[i] * 8;
    }
    int brow = tid >> 2, bseg = tid & 3;
    int d = col0 + brow;                                   // < DIM always
    const __half* bp = w2h + ((size_t)e * DIM + d) * HPAD + bseg * 8;

    int w = tid >> 5, lane = tid & 31;
    int wm = w >> 1, wn = w & 1;
    int a_r = lane & 15, a_c = (lane >> 4) * 8;
    int b_r = ((lane >> 4) << 3) + (lane & 7);
    int b_c = ((lane >> 3) & 1) * 8;

    float acc[2][4][4];
#pragma unroll
    for (int ms = 0; ms < 2; ms++)
#pragma unroll
        for (int ns = 0; ns < 4; ns++)
#pragma unroll
            for (int i = 0; i < 4; i++) acc[ms][ns][i] = 0.f;

#pragma unroll
    for (int i = 0; i < 2; i++)
        cp16(smem_u32(&sA[0][arow[i]][aseg[i] * 8]), aptr[i]);
    cp16(smem_u32(&sB[0][brow][bseg * 8]), bp);
    cp_commit();

    const int NIT = HPAD / BK;   // 86
    int cur = 0;
    for (int it = 0; it < NIT; it++) {
        if (it + 1 < NIT) {
            int k0 = (it + 1) * BK;
            int nst = cur ^ 1;
#pragma unroll
            for (int i = 0; i < 2; i++)
                cp16(smem_u32(&sA[nst][arow[i]][aseg[i] * 8]), aptr[i] + k0);
            cp16(smem_u32(&sB[nst][brow][bseg * 8]), bp + k0);
            cp_commit();
            cp_wait1();
        } else {
            cp_wait0();
        }
        __syncthreads();

#pragma unroll
        for (int ks = 0; ks < 2; ks++) {
            unsigned a[2][4];
#pragma unroll
            for (int ms = 0; ms < 2; ms++) {
                int m = wm * 32 + ms * 16;
                ldsm_x4(smem_u32(&sA[cur][m + a_r][ks * 16 + a_c]),
                        a[ms][0], a[ms][1], a[ms][2], a[ms][3]);
            }
            unsigned br[4][2];
#pragma unroll
            for (int ns2 = 0; ns2 < 2; ns2++) {
                int nn = wn * 32 + ns2 * 16;
                unsigned r0, r1, r2, r3;
                ldsm_x4(smem_u32(&sB[cur][nn + b_r][ks * 16 + b_c]), r0, r1, r2, r3);
                br[ns2*2][0] = r0; br[ns2*2][1] = r1;
                br[ns2*2+1][0] = r2; br[ns2*2+1][1] = r3;
            }
#pragma unroll
            for (int ms = 0; ms < 2; ms++)
#pragma unroll
                for (int ns = 0; ns < 4; ns++)
                    mma_f16(acc[ms][ns], a[ms], br[ns][0], br[ns][1]);
        }
        __syncthreads();
        cur ^= 1;
    }

    int crow = lane >> 2, ccol = (lane & 3) * 2;
#pragma unroll
    for (int ms = 0; ms < 2; ms++) {
#pragma unroll
        for (int half_ = 0; half_ < 2; half_++) {
            int r = row0 + wm * 32 + ms * 16 + crow + half_ * 8;
            if (r < ne) {
                float* dst = g_y + (size_t)(base + r) * DIM;
#pragma unroll
                for (int ns = 0; ns < 4; ns++) {
                    int cc = col0 + wn * 32 + ns * 8 + ccol;
                    *(float2*)(dst + cc) =
                        make_float2(acc[ms][ns][half_ * 2], acc[ms][ns][half_ * 2 + 1]);
                }
            }
        }
    }
}

// ---------------- combine ----------------------------------------------------
__global__ void k_combine(float* __restrict__ out) {
    int tok = blockIdx.x;
    int tid = threadIdx.x;
    int r0 = g_rowof[2 * tok], r1 = g_rowof[2 * tok + 1];
    float w0 = g_wslot[2 * tok], w1 = g_wslot[2 * tok + 1];
    float4 y0 = ((const float4*)(g_y + (size_t)r0 * DIM))[tid];
    float4 y1 = ((const float4*)(g_y + (size_t)r1 * DIM))[tid];
    float4 o;
    o.x = w0 * y0.x + w1 * y1.x;
    o.y = w0 * y0.y + w1 * y1.y;
    o.z = w0 * y0.z + w1 * y1.z;
    o.w = w0 * y0.w + w1 * y1.w;
    ((float4*)(out + (size_t)tok * DIM))[tid] = o;
}

// ---------------- launch -----------------------------------------------------
extern "C" void kernel_launch(void* const* d_in, const int* in_sizes, int n_in,
                              void* d_out, int out_size) {
    const float* x  = (const float*)d_in[0];
    const float* Wg = (const float*)d_in[1];
    const float* W1 = (const float*)d_in[2];
    const float* W2 = (const float*)d_in[3];
    const float* W3 = (const float*)d_in[4];
    float* out = (float*)d_out;
    (void)in_sizes; (void)n_in; (void)out_size;

    __half *xh, *w1h, *w3h;
    cudaGetSymbolAddress((void**)&xh,  g_xh);
    cudaGetSymbolAddress((void**)&w1h, g_w1h);
    cudaGetSymbolAddress((void**)&w3h, g_w3h);
    __half* w2h;
    cudaGetSymbolAddress((void**)&w2h, g_w2h);

    const int NW2 = NEXP * HID * DIM / 2;        // 11,190,272
    k_zero    <<<1, 32>>>();
    k_route   <<<NTOK / 8, 256>>>(x, Wg);
    k_half    <<<1024, 256>>>((const float2*)x,  (__half2*)xh,  NTOK * DIM / 2);
    k_half    <<<4096, 256>>>((const float2*)W1, (__half2*)w1h, NW2);
    k_half    <<<4096, 256>>>((const float2*)W3, (__half2*)w3h, NW2);
    k_half_w2 <<<4096, 256>>>(W2);
    k_scan    <<<1, 32>>>();
    k_scatter <<<NSLOT / 256, 256>>>();
    k_gemm1   <<<dim3(HPAD / 64, NSLOT / 128, NEXP), 256>>>(xh, w1h, w3h);
    k_gemm2   <<<dim3(DIM / 64, NSLOT / 128, NEXP), 256>>>(w2h);
    k_combine <<<NTOK, 256>>>(out);
}

// round 5
// speedup vs baseline: 4.7067x; 1.0621x over previous
#include <cuda_runtime.h>
#include <cuda_fp16.h>
#include <math.h>
#include <stdint.h>

#define NTOK  4096
#define DIM   1024
#define HID   2732
#define HPAD  2752          // 43 * 64
#define NEXP  8
#define NSLOT 8192
#define BK    32            // K halves per k-block
#define LDSH  40            // smem row stride in halves (80B): conflict-free ldsm
#define NST   3
#define NXB1  43            // HPAD/64
#define NXB2  16            // DIM/64
#define NCTA  296           // 2 * 148 SMs

// smem layout (halves): A[3][128][LDSH] | B1[3][64][LDSH] | B3[3][64][LDSH]
#define ASTR  (128 * LDSH * 2)          // bytes per A stage
#define BSTR  (64 * LDSH * 2)           // bytes per B stage
#define B1OFF (3 * ASTR)
#define B3OFF (B1OFF + 3 * BSTR)
#define SM1SZ (B3OFF + 3 * BSTR)        // 61440
#define SM2SZ (B1OFF + 3 * BSTR)        // 46080

// ---------------- scratch (static device globals; no allocs allowed) --------
__device__ __half g_h  [(size_t)NSLOT * HPAD];          // 45 MB
__device__ __half g_xh [(size_t)NTOK * DIM];
__device__ __half g_w1h[(size_t)NEXP * HID * DIM];
__device__ __half g_w3h[(size_t)NEXP * HID * DIM];
__device__ __half g_w2h[(size_t)NEXP * DIM * HPAD];     // padded rows
__device__ int    g_expert[NSLOT];
__device__ float  g_wslot[NSLOT];
__device__ float  g_w[NSLOT];        // per sorted row: combine weight
__device__ int    g_tok[NSLOT];      // per sorted row: token id
__device__ int    g_counts[NEXP];
__device__ int    g_off[NEXP];
__device__ int    g_cursor[NEXP];
__device__ int    g_pe[80], g_prb[80];
__device__ int    g_nt1, g_nt2;
__device__ int    g_tick1, g_tick2;

// ---------------- PTX helpers ------------------------------------------------
__device__ __forceinline__ unsigned smem_u32(const void* p) {
    return (unsigned)__cvta_generic_to_shared(p);
}
__device__ __forceinline__ void cp16(unsigned dst, const void* src) {
    asm volatile("cp.async.cg.shared.global [%0], [%1], 16;" :: "r"(dst), "l"(src));
}
__device__ __forceinline__ void cp16z(unsigned dst, const void* src, int sz) {
    asm volatile("cp.async.cg.shared.global [%0], [%1], 16, %2;"
                 :: "r"(dst), "l"(src), "r"(sz));
}
__device__ __forceinline__ void cp_commit() { asm volatile("cp.async.commit_group;"); }
__device__ __forceinline__ void cp_wait1()  { asm volatile("cp.async.wait_group 1;"); }

__device__ __forceinline__ void ldsm_x4(unsigned addr, unsigned& r0, unsigned& r1,
                                        unsigned& r2, unsigned& r3) {
    asm volatile("ldmatrix.sync.aligned.m8n8.x4.shared.b16 {%0,%1,%2,%3}, [%4];"
                 : "=r"(r0), "=r"(r1), "=r"(r2), "=r"(r3) : "r"(addr));
}
__device__ __forceinline__ void mma_f16(float* c, const unsigned* a, unsigned b0, unsigned b1) {
    asm volatile(
        "mma.sync.aligned.m16n8k16.row.col.f32.f16.f16.f32 "
        "{%0,%1,%2,%3}, {%4,%5,%6,%7}, {%8,%9}, {%0,%1,%2,%3};"
        : "+f"(c[0]), "+f"(c[1]), "+f"(c[2]), "+f"(c[3])
        : "r"(a[0]), "r"(a[1]), "r"(a[2]), "r"(a[3]), "r"(b0), "r"(b1));
}

// ---------------- bookkeeping ------------------------------------------------
__global__ void k_zero() { if (threadIdx.x < NEXP) g_counts[threadIdx.x] = 0; }

__global__ void k_scan() {
    if (threadIdx.x == 0) {
        int s = 0, np = 0;
        for (int e = 0; e < NEXP; e++) {
            g_off[e] = s; g_cursor[e] = s;
            int c = g_counts[e];
            for (int rb = 0; rb * 128 < c; rb++) { g_pe[np] = e; g_prb[np] = rb; np++; }
            s += c;
        }
        g_nt1 = np * NXB1;
        g_nt2 = np * NXB2;
        g_tick1 = 0;
        g_tick2 = 0;
    }
}
__global__ void k_scatter() {
    int s = blockIdx.x * 256 + threadIdx.x;
    if (s < NSLOT) {
        int pos = atomicAdd(&g_cursor[g_expert[s]], 1);
        g_tok[pos] = s >> 1;
        g_w[pos]   = g_wslot[s];
    }
}
__global__ void k_zero_out(float4* out) {
    int i = blockIdx.x * 256 + threadIdx.x;
    int stride = gridDim.x * 256;
    const int n = NTOK * DIM / 4;
    for (; i < n; i += stride) out[i] = make_float4(0.f, 0.f, 0.f, 0.f);
}
// f32 -> fp16 (rne), 16B granularity
__global__ void k_half(const float4* __restrict__ src, uint2* __restrict__ dst, int n4) {
    int i = blockIdx.x * 256 + threadIdx.x;
    int stride = gridDim.x * 256;
    for (; i < n4; i += stride) {
        float4 v = src[i];
        __half2 a = __floats2half2_rn(v.x, v.y);
        __half2 b = __floats2half2_rn(v.z, v.w);
        uint2 o;
        o.x = *reinterpret_cast<unsigned*>(&a);
        o.y = *reinterpret_cast<unsigned*>(&b);
        dst[i] = o;
    }
}
// W2 [E*DIM][HID] f32 -> [E*DIM][HPAD] fp16 zero-padded
__global__ void k_half_w2(const float* __restrict__ W2) {
    const int R4 = HPAD / 4;             // 688
    int i = blockIdx.x * 256 + threadIdx.x;
    int stride = gridDim.x * 256;
    const int n = NEXP * DIM * R4;
    for (; i < n; i += stride) {
        int row = i / R4;
        int c4  = (i - row * R4) * 4;
        uint2 o = make_uint2(0u, 0u);
        if (c4 < HID) {
            float4 v = *(const float4*)(W2 + (size_t)row * HID + c4);
            __half2 a = __floats2half2_rn(v.x, v.y);
            __half2 b = __floats2half2_rn(v.z, v.w);
            o.x = *reinterpret_cast<unsigned*>(&a);
            o.y = *reinterpret_cast<unsigned*>(&b);
        }
        *(uint2*)(g_w2h + (size_t)row * HPAD + c4) = o;
    }
}

// ---------------- routing (f32) ---------------------------------------------
__global__ void k_route(const float* __restrict__ x, const float* __restrict__ wg) {
    __shared__ float4 s_wg[NEXP * DIM / 4];
    int tid = threadIdx.x;
    const float4* wg4 = (const float4*)wg;
    for (int i = tid; i < NEXP * DIM / 4; i += 256) s_wg[i] = wg4[i];
    __syncthreads();

    int warp = tid >> 5, lane = tid & 31;
    int tok = blockIdx.x * 8 + warp;
    if (tok >= NTOK) return;

    const float4* xr = (const float4*)(x + (size_t)tok * DIM);
    float acc[NEXP];
#pragma unroll
    for (int e = 0; e < NEXP; e++) acc[e] = 0.f;
    for (int j = lane; j < DIM / 4; j += 32) {
        float4 xv = xr[j];
#pragma unroll
        for (int e = 0; e < NEXP; e++) {
            float4 w = s_wg[e * (DIM / 4) + j];
            acc[e] += xv.x * w.x + xv.y * w.y + xv.z * w.z + xv.w * w.w;
        }
    }
#pragma unroll
    for (int e = 0; e < NEXP; e++)
        for (int o = 16; o; o >>= 1) acc[e] += __shfl_xor_sync(0xffffffffu, acc[e], o);

    if (lane == 0) {
        int e0 = 0;
#pragma unroll
        for (int e = 1; e < NEXP; e++) if (acc[e] > acc[e0]) e0 = e;
        int e1 = (e0 == 0) ? 1 : 0;
#pragma unroll
        for (int e = 0; e < NEXP; e++) if (e != e0 && acc[e] > acc[e1]) e1 = e;
        float p1  = expf(acc[e1] - acc[e0]);
        float inv = 1.f / (1.f + p1);
        g_expert[2 * tok]     = e0;  g_wslot[2 * tok]     = inv;
        g_expert[2 * tok + 1] = e1;  g_wslot[2 * tok + 1] = p1 * inv;
        atomicAdd(&g_counts[e0], 1);
        atomicAdd(&g_counts[e1], 1);
    }
}

// ---------------- GEMM1: h = silu(X@W1^T)*(X@W3^T), persistent fp16 ---------
__global__ void __launch_bounds__(256, 2)
k_gemm1(const __half* __restrict__ xh, const __half* __restrict__ w1h,
        const __half* __restrict__ w3h) {
    extern __shared__ __half sm[];
    uint32_t sb0 = smem_u32(sm);
    __shared__ int s_tile;

    int tid = threadIdx.x;
    int w = tid >> 5, lane = tid & 31;
    int wm = w >> 1, wn = w & 1;
    int a_r = lane & 15, a_c = (lane >> 4) * 8;
    int b_r = ((lane >> 4) << 3) + (lane & 7);
    int b_c = ((lane >> 3) & 1) * 8;

    int arow[2], aseg[2];
    uint32_t aW[2];
#pragma unroll
    for (int i = 0; i < 2; i++) {
        int c = tid + 256 * i;
        arow[i] = c >> 2; aseg[i] = c & 3;
        aW[i] = sb0 + 2 * (arow[i] * LDSH + aseg[i] * 8);
    }
    int brow = tid >> 2, bseg = tid & 3;
    uint32_t b1W = sb0 + B1OFF + 2 * (brow * LDSH + bseg * 8);
    uint32_t b3W = sb0 + B3OFF + 2 * (brow * LDSH + bseg * 8);

    for (;;) {
        if (tid == 0) s_tile = atomicAdd(&g_tick1, 1);
        __syncthreads();
        int t = s_tile;
        if (t >= g_nt1) break;
        int pi = t / NXB1, xb = t - pi * NXB1;
        int e = g_pe[pi], row0 = g_prb[pi] * 128;
        int ne = g_counts[e], base = g_off[e], col0 = xb * 64;

        const __half* aP[2];
#pragma unroll
        for (int i = 0; i < 2; i++)
            aP[i] = xh + (size_t)g_tok[base + min(row0 + arow[i], ne - 1)] * DIM + aseg[i] * 8;
        int n = col0 + brow;
        int nv = (n < HID) ? 16 : 0;
        int nc = min(n, HID - 1);
        const __half* b1p = w1h + ((size_t)e * HID + nc) * DIM + bseg * 8;
        const __half* b3p = w3h + ((size_t)e * HID + nc) * DIM + bseg * 8;

        float acc1[2][4][4], acc3[2][4][4];
#pragma unroll
        for (int ms = 0; ms < 2; ms++)
#pragma unroll
            for (int ns = 0; ns < 4; ns++)
#pragma unroll
                for (int i = 0; i < 4; i++) { acc1[ms][ns][i] = 0.f; acc3[ms][ns][i] = 0.f; }

        // prologue: k-blocks 0,1 -> stages 0,1
#pragma unroll
        for (int s = 0; s < 2; s++) {
#pragma unroll
            for (int i = 0; i < 2; i++) cp16(aW[i] + s * ASTR, aP[i] + s * BK);
            cp16z(b1W + s * BSTR, b1p + s * BK, nv);
            cp16z(b3W + s * BSTR, b3p + s * BK, nv);
            cp_commit();
        }

        const int NIT = DIM / BK;   // 32
        for (int it = 0; it < NIT; it++) {
            cp_wait1();
            __syncthreads();
            int pf = it + 2;
            if (pf < NIT) {
                int s2 = pf % NST;
#pragma unroll
                for (int i = 0; i < 2; i++) cp16(aW[i] + s2 * ASTR, aP[i] + pf * BK);
                cp16z(b1W + s2 * BSTR, b1p + pf * BK, nv);
                cp16z(b3W + s2 * BSTR, b3p + pf * BK, nv);
            }
            cp_commit();
            int st = it % NST;
            uint32_t aBase = sb0 + st * ASTR;
            uint32_t bBase1 = sb0 + B1OFF + st * BSTR;
            uint32_t bBase3 = sb0 + B3OFF + st * BSTR;
#pragma unroll
            for (int ks = 0; ks < 2; ks++) {
                unsigned a[2][4];
#pragma unroll
                for (int ms = 0; ms < 2; ms++) {
                    int m = wm * 32 + ms * 16;
                    ldsm_x4(aBase + 2 * ((m + a_r) * LDSH + ks * 16 + a_c),
                            a[ms][0], a[ms][1], a[ms][2], a[ms][3]);
                }
                unsigned b1r[4][2], b3r[4][2];
#pragma unroll
                for (int ns2 = 0; ns2 < 2; ns2++) {
                    int nn = wn * 32 + ns2 * 16;
                    unsigned r0, r1, r2, r3;
                    ldsm_x4(bBase1 + 2 * ((nn + b_r) * LDSH + ks * 16 + b_c), r0, r1, r2, r3);
                    b1r[ns2*2][0] = r0; b1r[ns2*2][1] = r1;
                    b1r[ns2*2+1][0] = r2; b1r[ns2*2+1][1] = r3;
                    ldsm_x4(bBase3 + 2 * ((nn + b_r) * LDSH + ks * 16 + b_c), r0, r1, r2, r3);
                    b3r[ns2*2][0] = r0; b3r[ns2*2][1] = r1;
                    b3r[ns2*2+1][0] = r2; b3r[ns2*2+1][1] = r3;
                }
#pragma unroll
                for (int ms = 0; ms < 2; ms++)
#pragma unroll
                    for (int ns = 0; ns < 4; ns++) {
                        mma_f16(acc1[ms][ns], a[ms], b1r[ns][0], b1r[ns][1]);
                        mma_f16(acc3[ms][ns], a[ms], b3r[ns][0], b3r[ns][1]);
                    }
            }
        }

        // epilogue: SwiGLU -> fp16 h
        int crow = lane >> 2, ccol = (lane & 3) * 2;
#pragma unroll
        for (int ms = 0; ms < 2; ms++) {
#pragma unroll
            for (int half_ = 0; half_ < 2; half_++) {
                int r = row0 + wm * 32 + ms * 16 + crow + half_ * 8;
                if (r < ne) {
                    __half* dst = g_h + (size_t)(base + r) * HPAD;
#pragma unroll
                    for (int ns = 0; ns < 4; ns++) {
                        int cc = col0 + wn * 32 + ns * 8 + ccol;
                        float z0 = acc1[ms][ns][half_ * 2 + 0];
                        float z1 = acc1[ms][ns][half_ * 2 + 1];
                        float t0 = acc3[ms][ns][half_ * 2 + 0];
                        float t1 = acc3[ms][ns][half_ * 2 + 1];
                        float v0 = z0 / (1.f + __expf(-z0)) * t0;
                        float v1 = z1 / (1.f + __expf(-z1)) * t1;
                        *(__half2*)(dst + cc) = __float22half2_rn(make_float2(v0, v1));
                    }
                }
            }
        }
        __syncthreads();
    }
}

// ---------------- GEMM2: out[tok] += w * (h @ W2^T), persistent fp16 --------
__global__ void __launch_bounds__(256, 2)
k_gemm2(const __half* __restrict__ w2h, float* __restrict__ out) {
    extern __shared__ __half sm[];
    uint32_t sb0 = smem_u32(sm);
    __shared__ int s_tile;

    int tid = threadIdx.x;
    int w = tid >> 5, lane = tid & 31;
    int wm = w >> 1, wn = w & 1;
    int a_r = lane & 15, a_c = (lane >> 4) * 8;
    int b_r = ((lane >> 4) << 3) + (lane & 7);
    int b_c = ((lane >> 3) & 1) * 8;

    int arow[2], aseg[2];
    uint32_t aW[2];
#pragma unroll
    for (int i = 0; i < 2; i++) {
        int c = tid + 256 * i;
        arow[i] = c >> 2; aseg[i] = c & 3;
        aW[i] = sb0 + 2 * (arow[i] * LDSH + aseg[i] * 8);
    }
    int brow = tid >> 2, bseg = tid & 3;
    uint32_t bW = sb0 + B1OFF + 2 * (brow * LDSH + bseg * 8);

    for (;;) {
        if (tid == 0) s_tile = atomicAdd(&g_tick2, 1);
        __syncthreads();
        int t = s_tile;
        if (t >= g_nt2) break;
        int pi = t / NXB2, xb = t - pi * NXB2;
        int e = g_pe[pi], row0 = g_prb[pi] * 128;
        int ne = g_counts[e], base = g_off[e], col0 = xb * 64;

        const __half* aP[2];
#pragma unroll
        for (int i = 0; i < 2; i++)
            aP[i] = g_h + (size_t)(base + min(row0 + arow[i], ne - 1)) * HPAD + aseg[i] * 8;
        const __half* bp = w2h + ((size_t)e * DIM + col0 + brow) * HPAD + bseg * 8;

        float acc[2][4][4];
#pragma unroll
        for (int ms = 0; ms < 2; ms++)
#pragma unroll
            for (int ns = 0; ns < 4; ns++)
#pragma unroll
                for (int i = 0; i < 4; i++) acc[ms][ns][i] = 0.f;

#pragma unroll
        for (int s = 0; s < 2; s++) {
#pragma unroll
            for (int i = 0; i < 2; i++) cp16(aW[i] + s * ASTR, aP[i] + s * BK);
            cp16(bW + s * BSTR, bp + s * BK);
            cp_commit();
        }

        const int NIT = HPAD / BK;   // 86
        for (int it = 0; it < NIT; it++) {
            cp_wait1();
            __syncthreads();
            int pf = it + 2;
            if (pf < NIT) {
                int s2 = pf % NST;
#pragma unroll
                for (int i = 0; i < 2; i++) cp16(aW[i] + s2 * ASTR, aP[i] + pf * BK);
                cp16(bW + s2 * BSTR, bp + pf * BK);
            }
            cp_commit();
            int st = it % NST;
            uint32_t aBase = sb0 + st * ASTR;
            uint32_t bBase = sb0 + B1OFF + st * BSTR;
#pragma unroll
            for (int ks = 0; ks < 2; ks++) {
                unsigned a[2][4];
#pragma unroll
                for (int ms = 0; ms < 2; ms++) {
                    int m = wm * 32 + ms * 16;
                    ldsm_x4(aBase + 2 * ((m + a_r) * LDSH + ks * 16 + a_c),
                            a[ms][0], a[ms][1], a[ms][2], a[ms][3]);
                }
                unsigned br[4][2];
#pragma unroll
                for (int ns2 = 0; ns2 < 2; ns2++) {
                    int nn = wn * 32 + ns2 * 16;
                    unsigned r0, r1, r2, r3;
                    ldsm_x4(bBase + 2 * ((nn + b_r) * LDSH + ks * 16 + b_c), r0, r1, r2, r3);
                    br[ns2*2][0] = r0; br[ns2*2][1] = r1;
                    br[ns2*2+1][0] = r2; br[ns2*2+1][1] = r3;
                }
#pragma unroll
                for (int ms = 0; ms < 2; ms++)
#pragma unroll
                    for (int ns = 0; ns < 4; ns++)
                        mma_f16(acc[ms][ns], a[ms], br[ns][0], br[ns][1]);
            }
        }

        // epilogue: scale by combine weight, atomically accumulate into out
        int crow = lane >> 2, ccol = (lane & 3) * 2;
#pragma unroll
        for (int ms = 0; ms < 2; ms++) {
#pragma unroll
            for (int half_ = 0; half_ < 2; half_++) {
                int r = row0 + wm * 32 + ms * 16 + crow + half_ * 8;
                if (r < ne) {
                    int pos = base + r;
                    float wgt = g_w[pos];
                    float* dst = out + (size_t)g_tok[pos] * DIM;
#pragma unroll
                    for (int ns = 0; ns < 4; ns++) {
                        int cc = col0 + wn * 32 + ns * 8 + ccol;
                        atomicAdd(dst + cc,     wgt * acc[ms][ns][half_ * 2 + 0]);
                        atomicAdd(dst + cc + 1, wgt * acc[ms][ns][half_ * 2 + 1]);
                    }
                }
            }
        }
        __syncthreads();
    }
}

// ---------------- launch -----------------------------------------------------
extern "C" void kernel_launch(void* const* d_in, const int* in_sizes, int n_in,
                              void* d_out, int out_size) {
    const float* x  = (const float*)d_in[0];
    const float* Wg = (const float*)d_in[1];
    const float* W1 = (const float*)d_in[2];
    const float* W2 = (const float*)d_in[3];
    const float* W3 = (const float*)d_in[4];
    float* out = (float*)d_out;
    (void)in_sizes; (void)n_in; (void)out_size;

    cudaFuncSetAttribute(k_gemm1, cudaFuncAttributeMaxDynamicSharedMemorySize, SM1SZ);
    cudaFuncSetAttribute(k_gemm2, cudaFuncAttributeMaxDynamicSharedMemorySize, SM2SZ);

    __half *xh, *w1h, *w3h, *w2h;
    cudaGetSymbolAddress((void**)&xh,  g_xh);
    cudaGetSymbolAddress((void**)&w1h, g_w1h);
    cudaGetSymbolAddress((void**)&w3h, g_w3h);
    cudaGetSymbolAddress((void**)&w2h, g_w2h);

    const int NW4 = NEXP * HID * DIM / 4;       // 5,595,136
    k_zero     <<<1, 32>>>();
    k_route    <<<NTOK / 8, 256>>>(x, Wg);
    k_zero_out <<<1024, 256>>>((float4*)out);
    k_half     <<<512,  256>>>((const float4*)x,  (uint2*)xh,  NTOK * DIM / 4);
    k_half     <<<2048, 256>>>((const float4*)W1, (uint2*)w1h, NW4);
    k_half     <<<2048, 256>>>((const float4*)W3, (uint2*)w3h, NW4);
    k_half_w2  <<<2048, 256>>>(W2);
    k_scan     <<<1, 32>>>();
    k_scatter  <<<NSLOT / 256, 256>>>();
    k_gemm1    <<<NCTA, 256, SM1SZ>>>(xh, w1h, w3h);
    k_gemm2    <<<NCTA, 256, SM2SZ>>>(w2h, out);
}

// round 6
// speedup vs baseline: 4.9131x; 1.0439x over previous
#include <cuda_runtime.h>
#include <cuda_fp16.h>
#include <math.h>
#include <stdint.h>

#define NTOK  4096
#define DIM   1024
#define HID   2732
#define HPAD  2752          // 43 * 64
#define NEXP  8
#define NSLOT 8192
#define BK    32            // K halves per k-block
#define LDSH  40            // smem row stride in halves (80B): conflict-free ldsm
#define NST   4
#define NXB1  43            // HPAD/64
#define NXB2  16            // DIM/64
#define NCTA  296           // 2 * 148 SMs

// smem layout (halves): A[NST][128][LDSH] | B1[NST][64][LDSH] | B3[NST][64][LDSH]
#define ASTR  (128 * LDSH * 2)          // 10240 B per A stage
#define BSTR  (64 * LDSH * 2)           // 5120 B per B stage
#define B1OFF (NST * ASTR)
#define B3OFF (B1OFF + NST * BSTR)
#define SM1SZ (B3OFF + NST * BSTR)      // 81920
#define SM2SZ (B1OFF + NST * BSTR)      // 61440

// ---------------- scratch (static device globals; no allocs allowed) --------
__device__ __half g_h  [(size_t)NSLOT * HPAD];          // 45 MB
__device__ __half g_xh [(size_t)NTOK * DIM];
__device__ __half g_w1h[(size_t)NEXP * HID * DIM];
__device__ __half g_w3h[(size_t)NEXP * HID * DIM];
__device__ __half g_w2h[(size_t)NEXP * DIM * HPAD];     // padded rows
__device__ int    g_expert[NSLOT];
__device__ float  g_wslot[NSLOT];
__device__ float  g_w[NSLOT];        // per sorted row: combine weight
__device__ int    g_tok[NSLOT];      // per sorted row: token id
__device__ int    g_counts[NEXP];
__device__ int    g_off[NEXP];
__device__ int    g_cursor[NEXP];
__device__ int    g_pe[80], g_prb[80];
__device__ int    g_nt1, g_nt2;
__device__ int    g_tick1, g_tick2;

// ---------------- PTX helpers ------------------------------------------------
__device__ __forceinline__ unsigned smem_u32(const void* p) {
    return (unsigned)__cvta_generic_to_shared(p);
}
__device__ __forceinline__ void cp16(unsigned dst, const void* src) {
    asm volatile("cp.async.cg.shared.global [%0], [%1], 16;" :: "r"(dst), "l"(src));
}
__device__ __forceinline__ void cp16z(unsigned dst, const void* src, int sz) {
    asm volatile("cp.async.cg.shared.global [%0], [%1], 16, %2;"
                 :: "r"(dst), "l"(src), "r"(sz));
}
__device__ __forceinline__ void cp_commit() { asm volatile("cp.async.commit_group;"); }
__device__ __forceinline__ void cp_wait2()  { asm volatile("cp.async.wait_group 2;"); }

__device__ __forceinline__ void ldsm_x4(unsigned addr, unsigned& r0, unsigned& r1,
                                        unsigned& r2, unsigned& r3) {
    asm volatile("ldmatrix.sync.aligned.m8n8.x4.shared.b16 {%0,%1,%2,%3}, [%4];"
                 : "=r"(r0), "=r"(r1), "=r"(r2), "=r"(r3) : "r"(addr));
}
__device__ __forceinline__ void mma_f16(float* c, const unsigned* a, unsigned b0, unsigned b1) {
    asm volatile(
        "mma.sync.aligned.m16n8k16.row.col.f32.f16.f16.f32 "
        "{%0,%1,%2,%3}, {%4,%5,%6,%7}, {%8,%9}, {%0,%1,%2,%3};"
        : "+f"(c[0]), "+f"(c[1]), "+f"(c[2]), "+f"(c[3])
        : "r"(a[0]), "r"(a[1]), "r"(a[2]), "r"(a[3]), "r"(b0), "r"(b1));
}
__device__ __forceinline__ uint2 f4_to_h4(float4 v) {
    __half2 a = __floats2half2_rn(v.x, v.y);
    __half2 b = __floats2half2_rn(v.z, v.w);
    uint2 o;
    o.x = *reinterpret_cast<unsigned*>(&a);
    o.y = *reinterpret_cast<unsigned*>(&b);
    return o;
}

// ---------------- setup: zero counts + zero output ---------------------------
__global__ void k_setup(float4* __restrict__ out) {
    int i = blockIdx.x * 256 + threadIdx.x;
    if (i < NEXP) g_counts[i] = 0;
    int stride = gridDim.x * 256;
    const int n = NTOK * DIM / 4;
    for (int j = i; j < n; j += stride) out[j] = make_float4(0.f, 0.f, 0.f, 0.f);
}

// ---------------- weight converts (W1, W3 plain; W2 padded) ------------------
__global__ void k_wconv(const float4* __restrict__ W1, const float4* __restrict__ W3,
                        const float* __restrict__ W2) {
    int i0 = blockIdx.x * 256 + threadIdx.x;
    int S  = gridDim.x * 256;
    const int NW4 = NEXP * HID * DIM / 4;
    uint2* w1d = (uint2*)g_w1h;
    uint2* w3d = (uint2*)g_w3h;
    for (int i = i0; i < NW4; i += S) w1d[i] = f4_to_h4(W1[i]);
    for (int i = i0; i < NW4; i += S) w3d[i] = f4_to_h4(W3[i]);
    const int R4 = HPAD / 4;
    const int n2 = NEXP * DIM * R4;
    for (int i = i0; i < n2; i += S) {
        int row = i / R4;
        int c4  = (i - row * R4) * 4;
        uint2 o = make_uint2(0u, 0u);
        if (c4 < HID) o = f4_to_h4(*(const float4*)(W2 + (size_t)row * HID + c4));
        *(uint2*)(g_w2h + (size_t)row * HPAD + c4) = o;
    }
}

// ---------------- bookkeeping ------------------------------------------------
__global__ void k_scan() {
    if (threadIdx.x == 0) {
        int s = 0, np = 0;
        for (int e = 0; e < NEXP; e++) {
            g_off[e] = s; g_cursor[e] = s;
            int c = g_counts[e];
            for (int rb = 0; rb * 128 < c; rb++) { g_pe[np] = e; g_prb[np] = rb; np++; }
            s += c;
        }
        g_nt1 = np * NXB1;
        g_nt2 = np * NXB2;
        g_tick1 = 0;
        g_tick2 = 0;
    }
}
__global__ void k_scatter() {
    int s = blockIdx.x * 256 + threadIdx.x;
    if (s < NSLOT) {
        int pos = atomicAdd(&g_cursor[g_expert[s]], 1);
        g_tok[pos] = s >> 1;
        g_w[pos]   = g_wslot[s];
    }
}

// ---------------- routing (f32) + fused x -> fp16 convert --------------------
__global__ void k_route(const float* __restrict__ x, const float* __restrict__ wg) {
    __shared__ float4 s_wg[NEXP * DIM / 4];
    int tid = threadIdx.x;
    const float4* wg4 = (const float4*)wg;
    for (int i = tid; i < NEXP * DIM / 4; i += 256) s_wg[i] = wg4[i];
    __syncthreads();

    int warp = tid >> 5, lane = tid & 31;
    int tok = blockIdx.x * 8 + warp;
    if (tok >= NTOK) return;

    const float4* xr = (const float4*)(x + (size_t)tok * DIM);
    __half* xhrow = g_xh + (size_t)tok * DIM;
    float acc[NEXP];
#pragma unroll
    for (int e = 0; e < NEXP; e++) acc[e] = 0.f;
    for (int j = lane; j < DIM / 4; j += 32) {
        float4 xv = xr[j];
        *(uint2*)(xhrow + 4 * j) = f4_to_h4(xv);   // fused fp16 convert
#pragma unroll
        for (int e = 0; e < NEXP; e++) {
            float4 w = s_wg[e * (DIM / 4) + j];
            acc[e] += xv.x * w.x + xv.y * w.y + xv.z * w.z + xv.w * w.w;
        }
    }
#pragma unroll
    for (int e = 0; e < NEXP; e++)
        for (int o = 16; o; o >>= 1) acc[e] += __shfl_xor_sync(0xffffffffu, acc[e], o);

    if (lane == 0) {
        int e0 = 0;
#pragma unroll
        for (int e = 1; e < NEXP; e++) if (acc[e] > acc[e0]) e0 = e;
        int e1 = (e0 == 0) ? 1 : 0;
#pragma unroll
        for (int e = 0; e < NEXP; e++) if (e != e0 && acc[e] > acc[e1]) e1 = e;
        float p1  = expf(acc[e1] - acc[e0]);
        float inv = 1.f / (1.f + p1);
        g_expert[2 * tok]     = e0;  g_wslot[2 * tok]     = inv;
        g_expert[2 * tok + 1] = e1;  g_wslot[2 * tok + 1] = p1 * inv;
        atomicAdd(&g_counts[e0], 1);
        atomicAdd(&g_counts[e1], 1);
    }
}

// ---------------- GEMM1: h = silu(X@W1^T)*(X@W3^T), persistent fp16 ---------
__global__ void __launch_bounds__(256, 2)
k_gemm1(const __half* __restrict__ xh, const __half* __restrict__ w1h,
        const __half* __restrict__ w3h) {
    extern __shared__ __half sm[];
    uint32_t sb0 = smem_u32(sm);
    __shared__ int s_tile;

    int tid = threadIdx.x;
    int w = tid >> 5, lane = tid & 31;
    int wm = w >> 1, wn = w & 1;
    int a_r = lane & 15, a_c = (lane >> 4) * 8;
    int b_r = ((lane >> 4) << 3) + (lane & 7);
    int b_c = ((lane >> 3) & 1) * 8;

    int arow[2], aseg[2];
    uint32_t aW[2];
#pragma unroll
    for (int i = 0; i < 2; i++) {
        int c = tid + 256 * i;
        arow[i] = c >> 2; aseg[i] = c & 3;
        aW[i] = sb0 + 2 * (arow[i] * LDSH + aseg[i] * 8);
    }
    int brow = tid >> 2, bseg = tid & 3;
    uint32_t b1W = sb0 + B1OFF + 2 * (brow * LDSH + bseg * 8);
    uint32_t b3W = sb0 + B3OFF + 2 * (brow * LDSH + bseg * 8);

    for (;;) {
        if (tid == 0) s_tile = atomicAdd(&g_tick1, 1);
        __syncthreads();
        int t = s_tile;
        if (t >= g_nt1) break;
        int pi = t / NXB1, xb = t - pi * NXB1;
        int e = g_pe[pi], row0 = g_prb[pi] * 128;
        int ne = g_counts[e], base = g_off[e], col0 = xb * 64;

        const __half* aP[2];
#pragma unroll
        for (int i = 0; i < 2; i++)
            aP[i] = xh + (size_t)g_tok[base + min(row0 + arow[i], ne - 1)] * DIM + aseg[i] * 8;
        int n = col0 + brow;
        int nv = (n < HID) ? 16 : 0;
        int nc = min(n, HID - 1);
        const __half* b1p = w1h + ((size_t)e * HID + nc) * DIM + bseg * 8;
        const __half* b3p = w3h + ((size_t)e * HID + nc) * DIM + bseg * 8;

        float acc1[2][4][4], acc3[2][4][4];
#pragma unroll
        for (int ms = 0; ms < 2; ms++)
#pragma unroll
            for (int ns = 0; ns < 4; ns++)
#pragma unroll
                for (int i = 0; i < 4; i++) { acc1[ms][ns][i] = 0.f; acc3[ms][ns][i] = 0.f; }

        // prologue: k-blocks 0..2 -> stages 0..2
#pragma unroll
        for (int s = 0; s < NST - 1; s++) {
#pragma unroll
            for (int i = 0; i < 2; i++) cp16(aW[i] + s * ASTR, aP[i] + s * BK);
            cp16z(b1W + s * BSTR, b1p + s * BK, nv);
            cp16z(b3W + s * BSTR, b3p + s * BK, nv);
            cp_commit();
        }

        const int NIT = DIM / BK;   // 32
        for (int it = 0; it < NIT; it++) {
            cp_wait2();
            __syncthreads();
            int pf = it + NST - 1;
            if (pf < NIT) {
                int s2 = pf % NST;
#pragma unroll
                for (int i = 0; i < 2; i++) cp16(aW[i] + s2 * ASTR, aP[i] + pf * BK);
                cp16z(b1W + s2 * BSTR, b1p + pf * BK, nv);
                cp16z(b3W + s2 * BSTR, b3p + pf * BK, nv);
            }
            cp_commit();
            int st = it % NST;
            uint32_t aBase  = sb0 + st * ASTR;
            uint32_t bBase1 = sb0 + B1OFF + st * BSTR;
            uint32_t bBase3 = sb0 + B3OFF + st * BSTR;
#pragma unroll
            for (int ks = 0; ks < 2; ks++) {
                unsigned a[2][4];
#pragma unroll
                for (int ms = 0; ms < 2; ms++) {
                    int m = wm * 32 + ms * 16;
                    ldsm_x4(aBase + 2 * ((m + a_r) * LDSH + ks * 16 + a_c),
                            a[ms][0], a[ms][1], a[ms][2], a[ms][3]);
                }
                unsigned b1r[4][2], b3r[4][2];
#pragma unroll
                for (int ns2 = 0; ns2 < 2; ns2++) {
                    int nn = wn * 32 + ns2 * 16;
                    unsigned r0, r1, r2, r3;
                    ldsm_x4(bBase1 + 2 * ((nn + b_r) * LDSH + ks * 16 + b_c), r0, r1, r2, r3);
                    b1r[ns2*2][0] = r0; b1r[ns2*2][1] = r1;
                    b1r[ns2*2+1][0] = r2; b1r[ns2*2+1][1] = r3;
                    ldsm_x4(bBase3 + 2 * ((nn + b_r) * LDSH + ks * 16 + b_c), r0, r1, r2, r3);
                    b3r[ns2*2][0] = r0; b3r[ns2*2][1] = r1;
                    b3r[ns2*2+1][0] = r2; b3r[ns2*2+1][1] = r3;
                }
#pragma unroll
                for (int ms = 0; ms < 2; ms++)
#pragma unroll
                    for (int ns = 0; ns < 4; ns++) {
                        mma_f16(acc1[ms][ns], a[ms], b1r[ns][0], b1r[ns][1]);
                        mma_f16(acc3[ms][ns], a[ms], b3r[ns][0], b3r[ns][1]);
                    }
            }
        }

        // epilogue: SwiGLU -> fp16 h
        int crow = lane >> 2, ccol = (lane & 3) * 2;
#pragma unroll
        for (int ms = 0; ms < 2; ms++) {
#pragma unroll
            for (int half_ = 0; half_ < 2; half_++) {
                int r = row0 + wm * 32 + ms * 16 + crow + half_ * 8;
                if (r < ne) {
                    __half* dst = g_h + (size_t)(base + r) * HPAD;
#pragma unroll
                    for (int ns = 0; ns < 4; ns++) {
                        int cc = col0 + wn * 32 + ns * 8 + ccol;
                        float z0 = acc1[ms][ns][half_ * 2 + 0];
                        float z1 = acc1[ms][ns][half_ * 2 + 1];
                        float t0 = acc3[ms][ns][half_ * 2 + 0];
                        float t1 = acc3[ms][ns][half_ * 2 + 1];
                        float v0 = z0 / (1.f + __expf(-z0)) * t0;
                        float v1 = z1 / (1.f + __expf(-z1)) * t1;
                        *(__half2*)(dst + cc) = __float22half2_rn(make_float2(v0, v1));
                    }
                }
            }
        }
        __syncthreads();
    }
}

// ---------------- GEMM2: out[tok] += w * (h @ W2^T), persistent fp16 --------
__global__ void __launch_bounds__(256, 2)
k_gemm2(const __half* __restrict__ w2h, float* __restrict__ out) {
    extern __shared__ __half sm[];
    uint32_t sb0 = smem_u32(sm);
    __shared__ int s_tile;

    int tid = threadIdx.x;
    int w = tid >> 5, lane = tid & 31;
    int wm = w >> 1, wn = w & 1;
    int a_r = lane & 15, a_c = (lane >> 4) * 8;
    int b_r = ((lane >> 4) << 3) + (lane & 7);
    int b_c = ((lane >> 3) & 1) * 8;

    int arow[2], aseg[2];
    uint32_t aW[2];
#pragma unroll
    for (int i = 0; i < 2; i++) {
        int c = tid + 256 * i;
        arow[i] = c >> 2; aseg[i] = c & 3;
        aW[i] = sb0 + 2 * (arow[i] * LDSH + aseg[i] * 8);
    }
    int brow = tid >> 2, bseg = tid & 3;
    uint32_t bW = sb0 + B1OFF + 2 * (brow * LDSH + bseg * 8);

    for (;;) {
        if (tid == 0) s_tile = atomicAdd(&g_tick2, 1);
        __syncthreads();
        int t = s_tile;
        if (t >= g_nt2) break;
        int pi = t / NXB2, xb = t - pi * NXB2;
        int e = g_pe[pi], row0 = g_prb[pi] * 128;
        int ne = g_counts[e], base = g_off[e], col0 = xb * 64;

        const __half* aP[2];
#pragma unroll
        for (int i = 0; i < 2; i++)
            aP[i] = g_h + (size_t)(base + min(row0 + arow[i], ne - 1)) * HPAD + aseg[i] * 8;
        const __half* bp = w2h + ((size_t)e * DIM + col0 + brow) * HPAD + bseg * 8;

        float acc[2][4][4];
#pragma unroll
        for (int ms = 0; ms < 2; ms++)
#pragma unroll
            for (int ns = 0; ns < 4; ns++)
#pragma unroll
                for (int i = 0; i < 4; i++) acc[ms][ns][i] = 0.f;

#pragma unroll
        for (int s = 0; s < NST - 1; s++) {
#pragma unroll
            for (int i = 0; i < 2; i++) cp16(aW[i] + s * ASTR, aP[i] + s * BK);
            cp16(bW + s * BSTR, bp + s * BK);
            cp_commit();
        }

        const int NIT = HPAD / BK;   // 86
        for (int it = 0; it < NIT; it++) {
            cp_wait2();
            __syncthreads();
            int pf = it + NST - 1;
            if (pf < NIT) {
                int s2 = pf % NST;
#pragma unroll
                for (int i = 0; i < 2; i++) cp16(aW[i] + s2 * ASTR, aP[i] + pf * BK);
                cp16(bW + s2 * BSTR, bp + pf * BK);
            }
            cp_commit();
            int st = it % NST;
            uint32_t aBase = sb0 + st * ASTR;
            uint32_t bBase = sb0 + B1OFF + st * BSTR;
#pragma unroll
            for (int ks = 0; ks < 2; ks++) {
                unsigned a[2][4];
#pragma unroll
                for (int ms = 0; ms < 2; ms++) {
                    int m = wm * 32 + ms * 16;
                    ldsm_x4(aBase + 2 * ((m + a_r) * LDSH + ks * 16 + a_c),
                            a[ms][0], a[ms][1], a[ms][2], a[ms][3]);
                }
                unsigned br[4][2];
#pragma unroll
                for (int ns2 = 0; ns2 < 2; ns2++) {
                    int nn = wn * 32 + ns2 * 16;
                    unsigned r0, r1, r2, r3;
                    ldsm_x4(bBase + 2 * ((nn + b_r) * LDSH + ks * 16 + b_c), r0, r1, r2, r3);
                    br[ns2*2][0] = r0; br[ns2*2][1] = r1;
                    br[ns2*2+1][0] = r2; br[ns2*2+1][1] = r3;
                }
#pragma unroll
                for (int ms = 0; ms < 2; ms++)
#pragma unroll
                    for (int ns = 0; ns < 4; ns++)
                        mma_f16(acc[ms][ns], a[ms], br[ns][0], br[ns][1]);
            }
        }

        // epilogue: scale by combine weight, atomically accumulate into out
        int crow = lane >> 2, ccol = (lane & 3) * 2;
#pragma unroll
        for (int ms = 0; ms < 2; ms++) {
#pragma unroll
            for (int half_ = 0; half_ < 2; half_++) {
                int r = row0 + wm * 32 + ms * 16 + crow + half_ * 8;
                if (r < ne) {
                    int pos = base + r;
                    float wgt = g_w[pos];
                    float* dst = out + (size_t)g_tok[pos] * DIM;
#pragma unroll
                    for (int ns = 0; ns < 4; ns++) {
                        int cc = col0 + wn * 32 + ns * 8 + ccol;
                        atomicAdd(dst + cc,     wgt * acc[ms][ns][half_ * 2 + 0]);
                        atomicAdd(dst + cc + 1, wgt * acc[ms][ns][half_ * 2 + 1]);
                    }
                }
            }
        }
        __syncthreads();
    }
}

// ---------------- launch -----------------------------------------------------
extern "C" void kernel_launch(void* const* d_in, const int* in_sizes, int n_in,
                              void* d_out, int out_size) {
    const float* x  = (const float*)d_in[0];
    const float* Wg = (const float*)d_in[1];
    const float* W1 = (const float*)d_in[2];
    const float* W2 = (const float*)d_in[3];
    const float* W3 = (const float*)d_in[4];
    float* out = (float*)d_out;
    (void)in_sizes; (void)n_in; (void)out_size;

    cudaFuncSetAttribute(k_gemm1, cudaFuncAttributeMaxDynamicSharedMemorySize, SM1SZ);
    cudaFuncSetAttribute(k_gemm2, cudaFuncAttributeMaxDynamicSharedMemorySize, SM2SZ);

    __half *xh, *w1h, *w3h, *w2h;
    cudaGetSymbolAddress((void**)&xh,  g_xh);
    cudaGetSymbolAddress((void**)&w1h, g_w1h);
    cudaGetSymbolAddress((void**)&w3h, g_w3h);
    cudaGetSymbolAddress((void**)&w2h, g_w2h);

    k_setup   <<<1024, 256>>>((float4*)out);
    k_route   <<<NTOK / 8, 256>>>(x, Wg);
    k_wconv   <<<2048, 256>>>((const float4*)W1, (const float4*)W3, W2);
    k_scan    <<<1, 32>>>();
    k_scatter <<<NSLOT / 256, 256>>>();
    k_gemm1   <<<NCTA, 256, SM1SZ>>>(xh, w1h, w3h);
    k_gemm2   <<<NCTA, 256, SM2SZ>>>(w2h, out);
}